// round 1
// baseline (speedup 1.0000x reference)
#include <cuda_runtime.h>
#include <math.h>

#define BATCH 2
#define SEQ   2048
#define EMB   2048
#define NHEAD 16
#define HDIM  128
#define MTOT  (BATCH*SEQ)   // 4096
#define LOG2E 1.4426950408889634f

// ---- scratch (static device allocations; allowed per harness rules) ----
__device__ float g_Q[MTOT*EMB];
__device__ float g_K[MTOT*EMB];
__device__ float g_V[MTOT*EMB];
__device__ float g_ctx[MTOT*EMB];

// ============================================================================
// SGEMM NT: C[M,N] = A[M,K] * B[N,K]^T   (both row-major, K contiguous)
// BM=BN=128, BK=16, 256 threads, 8x8 microtile. M,N % 128 == 0, K % 16 == 0.
// ============================================================================
__global__ __launch_bounds__(256) void sgemm_nt(const float* __restrict__ A,
                                                const float* __restrict__ B,
                                                float* __restrict__ C,
                                                int M, int N, int K)
{
    __shared__ float As[16][132];   // [k][m], padded: conflict-free transpose store,
    __shared__ float Bs[16][132];   // 132*4B keeps float4-aligned rows (528 % 16 == 0)

    const int tid = threadIdx.x;
    const int m0 = blockIdx.y * 128;
    const int n0 = blockIdx.x * 128;
    const int ty = tid >> 4, tx = tid & 15;
    const int r0 = ty * 8, c0 = tx * 8;

    float acc[8][8] = {};

    for (int k0 = 0; k0 < K; k0 += 16) {
        #pragma unroll
        for (int it = 0; it < 2; it++) {
            int id  = tid + it * 256;          // 0..511
            int row = id >> 2;                 // 0..127
            int c4  = (id & 3) * 4;            // 0,4,8,12
            float4 av = *(const float4*)&A[(long)(m0 + row) * K + k0 + c4];
            As[c4+0][row] = av.x; As[c4+1][row] = av.y;
            As[c4+2][row] = av.z; As[c4+3][row] = av.w;
            float4 bv = *(const float4*)&B[(long)(n0 + row) * K + k0 + c4];
            Bs[c4+0][row] = bv.x; Bs[c4+1][row] = bv.y;
            Bs[c4+2][row] = bv.z; Bs[c4+3][row] = bv.w;
        }
        __syncthreads();

        #pragma unroll
        for (int kk = 0; kk < 16; kk++) {
            float a[8], b[8];
            *(float4*)&a[0] = *(const float4*)&As[kk][r0];
            *(float4*)&a[4] = *(const float4*)&As[kk][r0 + 4];
            *(float4*)&b[0] = *(const float4*)&Bs[kk][c0];
            *(float4*)&b[4] = *(const float4*)&Bs[kk][c0 + 4];
            #pragma unroll
            for (int i = 0; i < 8; i++)
                #pragma unroll
                for (int j = 0; j < 8; j++)
                    acc[i][j] = fmaf(a[i], b[j], acc[i][j]);
        }
        __syncthreads();
    }

    #pragma unroll
    for (int i = 0; i < 8; i++) {
        float4* p = (float4*)&C[(long)(m0 + r0 + i) * N + n0 + c0];
        p[0] = make_float4(acc[i][0], acc[i][1], acc[i][2], acc[i][3]);
        p[1] = make_float4(acc[i][4], acc[i][5], acc[i][6], acc[i][7]);
    }
}

// ============================================================================
// RoPE (in-place on Q and K, [B,S,E] layout). Also folds 1/sqrt(D) into Q.
// One thread per (b,s,h,i) rotation pair, i in [0,64).
// ============================================================================
__global__ void rope_kernel(float* __restrict__ q, float* __restrict__ k)
{
    int idx = blockIdx.x * blockDim.x + threadIdx.x;   // 0 .. MTOT*1024-1
    int p  = idx & 1023;            // h*64 + i
    int bs = idx >> 10;             // 0..4095
    int s  = bs & (SEQ - 1);
    int h  = p >> 6, i = p & 63;

    // freq = 10000^(-i/64) = 2^(-i * log2(10000)/64)
    float freq = exp2f(-(float)i * 0.20762050593046010f);
    float ang  = (float)s * freq;
    float sn, cs;
    sincosf(ang, &sn, &cs);

    long base = (long)bs * EMB + h * HDIM + i;
    const float qscale = 0.08838834764831845f;  // 1/sqrt(128)

    float q1 = q[base], q2 = q[base + 64];
    q[base]      = (q1 * cs - q2 * sn) * qscale;
    q[base + 64] = (q2 * cs + q1 * sn) * qscale;

    float k1 = k[base], k2 = k[base + 64];
    k[base]      = k1 * cs - k2 * sn;
    k[base + 64] = k2 * cs + k1 * sn;
}

// ============================================================================
// Flash attention, causal. BM=BN=64, D=128, 256 threads (16x16).
// Each thread: S-tile 4x4 (rows ty*4.., cols tx*4..), O-tile 4x8 (cols tx*8..).
// Q/K stored transposed [d][row] (stride 65), V natural [row][d] (stride 128),
// P staged transposed [col][row] (stride 65).
// ============================================================================
__global__ __launch_bounds__(256) void flash_kernel(const float* __restrict__ Q,
                                                    const float* __restrict__ K,
                                                    const float* __restrict__ V,
                                                    const float* __restrict__ mask,
                                                    float* __restrict__ ctx)
{
    extern __shared__ float sm[];
    float* Qs = sm;                 // [128][65]
    float* Ks = Qs + 128 * 65;      // [128][65]
    float* Vs = Ks + 128 * 65;      // [64][128]
    float* Ps = Vs + 64 * 128;      // [64][65]
    float* mv = Ps + 64 * 65;       // [64]

    const int tid = threadIdx.x;
    const int ty = tid >> 4, tx = tid & 15;
    const int r0 = ty * 4, c0 = tx * 4, co = tx * 8;
    const int q0 = blockIdx.x * 64;
    const int h  = blockIdx.y;
    const int b  = blockIdx.z;

    // load Q tile transposed
    const float* Qg = Q + ((long)(b * SEQ + q0)) * EMB + h * HDIM;
    #pragma unroll
    for (int it = 0; it < 8; it++) {
        int id = tid + it * 256;           // 0..2047
        int r  = id >> 5;                  // 0..63
        int c4 = (id & 31) * 4;            // 0..124
        float4 v = *(const float4*)&Qg[(long)r * EMB + c4];
        Qs[(c4+0)*65 + r] = v.x; Qs[(c4+1)*65 + r] = v.y;
        Qs[(c4+2)*65 + r] = v.z; Qs[(c4+3)*65 + r] = v.w;
    }

    float O[4][8] = {};
    float m_i[4], l_i[4];
    #pragma unroll
    for (int i = 0; i < 4; i++) { m_i[i] = -INFINITY; l_i[i] = 0.f; }

    const int nkb = (q0 >> 6) + 1;
    for (int kb = 0; kb < nkb; kb++) {
        __syncthreads();  // previous iter's Ps/Vs reads done before overwrite
        const float* Kg = K + ((long)(b * SEQ + kb * 64)) * EMB + h * HDIM;
        const float* Vg = V + ((long)(b * SEQ + kb * 64)) * EMB + h * HDIM;
        #pragma unroll
        for (int it = 0; it < 8; it++) {
            int id = tid + it * 256;
            int r  = id >> 5;
            int c4 = (id & 31) * 4;
            float4 kv = *(const float4*)&Kg[(long)r * EMB + c4];
            Ks[(c4+0)*65 + r] = kv.x; Ks[(c4+1)*65 + r] = kv.y;
            Ks[(c4+2)*65 + r] = kv.z; Ks[(c4+3)*65 + r] = kv.w;
            float4 vv = *(const float4*)&Vg[(long)r * EMB + c4];
            *(float4*)&Vs[r * 128 + c4] = vv;
        }
        if (tid < 64) mv[tid] = (1.0f - mask[b * SEQ + kb * 64 + tid]) * -1e9f;
        __syncthreads();

        // S = Q @ K^T  (4x4 per thread)
        float s[4][4] = {};
        #pragma unroll 4
        for (int kk = 0; kk < 128; kk++) {
            float a[4], bb[4];
            #pragma unroll
            for (int i = 0; i < 4; i++) a[i]  = Qs[kk * 65 + r0 + i];
            #pragma unroll
            for (int j = 0; j < 4; j++) bb[j] = Ks[kk * 65 + c0 + j];
            #pragma unroll
            for (int i = 0; i < 4; i++)
                #pragma unroll
                for (int j = 0; j < 4; j++)
                    s[i][j] = fmaf(a[i], bb[j], s[i][j]);
        }

        // padding mask + causal mask (diagonal block only)
        #pragma unroll
        for (int i = 0; i < 4; i++)
            #pragma unroll
            for (int j = 0; j < 4; j++)
                s[i][j] += mv[c0 + j];
        if (kb == nkb - 1) {
            #pragma unroll
            for (int i = 0; i < 4; i++)
                #pragma unroll
                for (int j = 0; j < 4; j++)
                    if (kb * 64 + c0 + j > q0 + r0 + i) s[i][j] = -INFINITY;
        }

        // online softmax update
        float alpha[4];
        #pragma unroll
        for (int i = 0; i < 4; i++) {
            float rm = fmaxf(fmaxf(s[i][0], s[i][1]), fmaxf(s[i][2], s[i][3]));
            #pragma unroll
            for (int o = 1; o < 16; o <<= 1)
                rm = fmaxf(rm, __shfl_xor_sync(0xffffffffu, rm, o));
            float mnew = fmaxf(m_i[i], rm);
            alpha[i] = exp2f((m_i[i] - mnew) * LOG2E);
            m_i[i] = mnew;
        }
        #pragma unroll
        for (int i = 0; i < 4; i++) {
            float rs = 0.f;
            #pragma unroll
            for (int j = 0; j < 4; j++) {
                float pv = exp2f((s[i][j] - m_i[i]) * LOG2E);
                s[i][j] = pv;
                rs += pv;
            }
            #pragma unroll
            for (int o = 1; o < 16; o <<= 1)
                rs += __shfl_xor_sync(0xffffffffu, rs, o);
            l_i[i] = l_i[i] * alpha[i] + rs;
            #pragma unroll
            for (int jj = 0; jj < 8; jj++) O[i][jj] *= alpha[i];
        }

        // stage P transposed [col][row]
        #pragma unroll
        for (int i = 0; i < 4; i++)
            #pragma unroll
            for (int j = 0; j < 4; j++)
                Ps[(c0 + j) * 65 + (r0 + i)] = s[i][j];
        __syncthreads();

        // O += P @ V
        #pragma unroll 2
        for (int j = 0; j < 64; j++) {
            float a2[4];
            #pragma unroll
            for (int i = 0; i < 4; i++) a2[i] = Ps[j * 65 + r0 + i];
            float4 v0 = *(const float4*)&Vs[j * 128 + co];
            float4 v1 = *(const float4*)&Vs[j * 128 + co + 4];
            #pragma unroll
            for (int i = 0; i < 4; i++) {
                O[i][0] = fmaf(a2[i], v0.x, O[i][0]);
                O[i][1] = fmaf(a2[i], v0.y, O[i][1]);
                O[i][2] = fmaf(a2[i], v0.z, O[i][2]);
                O[i][3] = fmaf(a2[i], v0.w, O[i][3]);
                O[i][4] = fmaf(a2[i], v1.x, O[i][4]);
                O[i][5] = fmaf(a2[i], v1.y, O[i][5]);
                O[i][6] = fmaf(a2[i], v1.z, O[i][6]);
                O[i][7] = fmaf(a2[i], v1.w, O[i][7]);
            }
        }
    }

    // epilogue: normalize + write to ctx [B,S,E]
    float* Og = ctx + ((long)(b * SEQ + q0)) * EMB + h * HDIM;
    #pragma unroll
    for (int i = 0; i < 4; i++) {
        float inv = 1.0f / l_i[i];
        float4 o0 = make_float4(O[i][0]*inv, O[i][1]*inv, O[i][2]*inv, O[i][3]*inv);
        float4 o1 = make_float4(O[i][4]*inv, O[i][5]*inv, O[i][6]*inv, O[i][7]*inv);
        *(float4*)&Og[(long)(r0 + i) * EMB + co]     = o0;
        *(float4*)&Og[(long)(r0 + i) * EMB + co + 4] = o1;
    }
}

// ============================================================================
// launch
// ============================================================================
extern "C" void kernel_launch(void* const* d_in, const int* in_sizes, int n_in,
                              void* d_out, int out_size)
{
    const float* x    = (const float*)d_in[0];
    const float* mask = (const float*)d_in[1];
    const float* Wq   = (const float*)d_in[2];
    const float* Wk   = (const float*)d_in[3];
    const float* Wv   = (const float*)d_in[4];
    const float* Wo   = (const float*)d_in[5];
    float* out = (float*)d_out;

    float *qp, *kp, *vp, *cp;
    cudaGetSymbolAddress((void**)&qp, g_Q);
    cudaGetSymbolAddress((void**)&kp, g_K);
    cudaGetSymbolAddress((void**)&vp, g_V);
    cudaGetSymbolAddress((void**)&cp, g_ctx);

    dim3 gg(EMB / 128, MTOT / 128);
    sgemm_nt<<<gg, 256>>>(x, Wq, qp, MTOT, EMB, EMB);
    sgemm_nt<<<gg, 256>>>(x, Wk, kp, MTOT, EMB, EMB);
    sgemm_nt<<<gg, 256>>>(x, Wv, vp, MTOT, EMB, EMB);

    rope_kernel<<<(MTOT * 1024) / 256, 256>>>(qp, kp);

    const int smem_bytes = (128*65 + 128*65 + 64*128 + 64*65 + 64) * 4;  // 116224
    cudaFuncSetAttribute(flash_kernel, cudaFuncAttributeMaxDynamicSharedMemorySize,
                         smem_bytes);
    flash_kernel<<<dim3(SEQ / 64, NHEAD, BATCH), 256, smem_bytes>>>(qp, kp, vp, mask, cp);

    sgemm_nt<<<gg, 256>>>(cp, Wo, out, MTOT, EMB, EMB);
}

// round 3
// speedup vs baseline: 1.5425x; 1.5425x over previous
#include <cuda_runtime.h>
#include <cuda_bf16.h>
#include <math.h>
#include <cstdint>

#define BATCH 2
#define SEQ   2048
#define EMB   2048
#define NHEAD 16
#define HDIM  128
#define MTOT  (BATCH*SEQ)   // 4096
#define KP    (3*EMB)       // 6144 (tripled K for bf16 3-term split)
#define LOG2E 1.4426950408889634f

// ---- scratch (static device allocations) ----
__device__ float g_Q[MTOT*EMB];
__device__ float g_K[MTOT*EMB];
__device__ float g_V[MTOT*EMB];
__device__ float g_ctx[MTOT*EMB];
__device__ __nv_bfloat16 g_Ax[(size_t)MTOT*KP];   // split x / split ctx (reused)
__device__ __nv_bfloat16 g_Wqs[(size_t)EMB*KP];
__device__ __nv_bfloat16 g_Wks[(size_t)EMB*KP];
__device__ __nv_bfloat16 g_Wvs[(size_t)EMB*KP];
__device__ __nv_bfloat16 g_Wos[(size_t)EMB*KP];

// ============================================================================
// helpers
// ============================================================================
__device__ __forceinline__ uint32_t smem_u32(const void* p) {
    uint32_t a;
    asm("{ .reg .u64 t; cvta.to.shared.u64 t, %1; cvt.u32.u64 %0, t; }"
        : "=r"(a) : "l"(p));
    return a;
}
__device__ __forceinline__ void cp16(uint32_t dst, const void* src) {
    asm volatile("cp.async.cg.shared.global [%0], [%1], 16;\n" :: "r"(dst), "l"(src));
}
#define CP_COMMIT() asm volatile("cp.async.commit_group;" ::: "memory")
#define CP_WAIT(n)  asm volatile("cp.async.wait_group %0;" :: "n"(n) : "memory")

__device__ __forceinline__ void ldsm_x4(uint32_t (&r)[4], uint32_t addr) {
    asm volatile("ldmatrix.sync.aligned.m8n8.x4.shared.b16 {%0,%1,%2,%3}, [%4];"
                 : "=r"(r[0]), "=r"(r[1]), "=r"(r[2]), "=r"(r[3]) : "r"(addr));
}
__device__ __forceinline__ void ldsm_x2(uint32_t (&r)[2], uint32_t addr) {
    asm volatile("ldmatrix.sync.aligned.m8n8.x2.shared.b16 {%0,%1}, [%2];"
                 : "=r"(r[0]), "=r"(r[1]) : "r"(addr));
}
__device__ __forceinline__ void mma_bf16(float (&d)[4], const uint32_t (&a)[4],
                                         const uint32_t (&b)[2]) {
    asm volatile(
        "mma.sync.aligned.m16n8k16.row.col.f32.bf16.bf16.f32 "
        "{%0,%1,%2,%3}, {%4,%5,%6,%7}, {%8,%9}, {%0,%1,%2,%3};"
        : "+f"(d[0]), "+f"(d[1]), "+f"(d[2]), "+f"(d[3])
        : "r"(a[0]), "r"(a[1]), "r"(a[2]), "r"(a[3]), "r"(b[0]), "r"(b[1]));
}

// ============================================================================
// split: fp32 [R,2048] -> bf16 [R,6144]; A-pattern [hi,lo,hi], B-pattern [hi,hi,lo]
// ============================================================================
__global__ void split_bf16(const float* __restrict__ in, __nv_bfloat16* __restrict__ out,
                           int aPattern)
{
    int idx = blockIdx.x * blockDim.x + threadIdx.x;
    int r = idx >> 9;
    int c = (idx & 511) << 2;
    float4 v = *(const float4*)&in[((size_t)r << 11) + c];
    __nv_bfloat162 h01 = __floats2bfloat162_rn(v.x, v.y);
    __nv_bfloat162 h23 = __floats2bfloat162_rn(v.z, v.w);
    float2 f01 = __bfloat1622float2(h01);
    float2 f23 = __bfloat1622float2(h23);
    __nv_bfloat162 l01 = __floats2bfloat162_rn(v.x - f01.x, v.y - f01.y);
    __nv_bfloat162 l23 = __floats2bfloat162_rn(v.z - f23.x, v.w - f23.y);
    uint2 H, L;
    H.x = *(uint32_t*)&h01; H.y = *(uint32_t*)&h23;
    L.x = *(uint32_t*)&l01; L.y = *(uint32_t*)&l23;
    size_t ob = (size_t)r * KP + c;
    *(uint2*)&out[ob] = H;
    *(uint2*)&out[ob + 2048] = aPattern ? L : H;
    *(uint2*)&out[ob + 4096] = aPattern ? H : L;
}

// ============================================================================
// HMMA bf16 GEMM: C[M,N] fp32 = A'[M,KP] * B'[N,KP]^T (both row-major, K contig)
// Tile 128x128, BK=32, 256 threads = 8 warps (4x2), warp tile 32x64,
// 3-stage cp.async pipeline, padded smem rows (40 bf16 = 80B).
// ============================================================================
#define BKG       32
#define GSTRIDE   40                         // bf16 elems per smem row (80B)
#define TILE_B    (128 * GSTRIDE * 2)        // 10240 B (one matrix)
#define STAGE_B   (2 * TILE_B)               // 20480 B (A + B)
#define G_NCH     (KP / BKG)                 // 192
#define G_SMEM    (3 * STAGE_B)              // 61440

__device__ __forceinline__ void g_load_stage(uint32_t sbase,
                                             const __nv_bfloat16* __restrict__ A,
                                             const __nv_bfloat16* __restrict__ B,
                                             int m0, int n0, int c, int tid)
{
    const __nv_bfloat16* Ag = A + (size_t)m0 * KP + c * BKG;
    const __nv_bfloat16* Bg = B + (size_t)n0 * KP + c * BKG;
    #pragma unroll
    for (int i = 0; i < 2; i++) {
        int id = tid + i * 256;              // 0..511
        int r  = id >> 2;                    // row 0..127
        int ch = id & 3;                     // 16B chunk in 64B row
        cp16(sbase + r * 80 + ch * 16, Ag + (size_t)r * KP + ch * 8);
        cp16(sbase + TILE_B + r * 80 + ch * 16, Bg + (size_t)r * KP + ch * 8);
    }
}

__global__ __launch_bounds__(256) void gemm_bf16s(const __nv_bfloat16* __restrict__ A,
                                                  const __nv_bfloat16* __restrict__ B,
                                                  float* __restrict__ C, int N)
{
    extern __shared__ __align__(128) char smem[];
    const uint32_t sb = smem_u32(smem);
    const int tid  = threadIdx.x;
    const int lane = tid & 31;
    const int w    = tid >> 5;
    const int wr   = w >> 1;                 // 0..3  (row of warp grid)
    const int wc   = w & 1;                  // 0..1  (col of warp grid)
    const int m0 = blockIdx.y * 128;
    const int n0 = blockIdx.x * 128;

    float acc[2][8][4] = {};

    // ldmatrix base offsets (within a stage)
    const uint32_t aoff = (uint32_t)((wr * 32 + (lane & 15)) * GSTRIDE + (lane >> 4) * 8) * 2;
    const uint32_t boff = TILE_B +
        (uint32_t)((wc * 64 + (lane & 7)) * GSTRIDE + ((lane >> 3) & 1) * 8) * 2;

    // prologue: prefetch chunks 0,1
    g_load_stage(sb, A, B, m0, n0, 0, tid);
    CP_COMMIT();
    g_load_stage(sb + STAGE_B, A, B, m0, n0, 1, tid);
    CP_COMMIT();

    for (int c = 0; c < G_NCH; c++) {
        if (c == G_NCH - 1) { CP_WAIT(0); } else { CP_WAIT(1); }
        __syncthreads();

        const int cn = c + 2;
        if (cn < G_NCH) {
            g_load_stage(sb + (cn % 3) * STAGE_B, A, B, m0, n0, cn, tid);
            CP_COMMIT();
        }

        const uint32_t stg = sb + (c % 3) * STAGE_B;
        #pragma unroll
        for (int ks = 0; ks < 2; ks++) {          // two k16 steps in BK=32
            uint32_t af[2][4];
            #pragma unroll
            for (int mt = 0; mt < 2; mt++)
                ldsm_x4(af[mt], stg + aoff + (uint32_t)(mt * 16 * GSTRIDE + ks * 16) * 2);
            uint32_t bf[8][2];
            #pragma unroll
            for (int nt = 0; nt < 8; nt++)
                ldsm_x2(bf[nt], stg + boff + (uint32_t)(nt * 8 * GSTRIDE + ks * 16) * 2);
            #pragma unroll
            for (int mt = 0; mt < 2; mt++)
                #pragma unroll
                for (int nt = 0; nt < 8; nt++)
                    mma_bf16(acc[mt][nt], af[mt], bf[nt]);
        }
        __syncthreads();
    }

    // epilogue
    const int r0 = m0 + wr * 32 + (lane >> 2);
    const int c0 = n0 + wc * 64 + (lane & 3) * 2;
    #pragma unroll
    for (int mt = 0; mt < 2; mt++)
        #pragma unroll
        for (int nt = 0; nt < 8; nt++) {
            float* p0 = &C[(size_t)(r0 + mt * 16) * N + c0 + nt * 8];
            float* p1 = &C[(size_t)(r0 + mt * 16 + 8) * N + c0 + nt * 8];
            *(float2*)p0 = make_float2(acc[mt][nt][0], acc[mt][nt][1]);
            *(float2*)p1 = make_float2(acc[mt][nt][2], acc[mt][nt][3]);
        }
}

// ============================================================================
// RoPE (in-place, folds 1/sqrt(D) into Q)
// ============================================================================
__global__ void rope_kernel(float* __restrict__ q, float* __restrict__ k)
{
    int idx = blockIdx.x * blockDim.x + threadIdx.x;
    int p  = idx & 1023;
    int bs = idx >> 10;
    int s  = bs & (SEQ - 1);
    int h  = p >> 6, i = p & 63;

    float freq = exp2f(-(float)i * 0.20762050593046010f);
    float ang  = (float)s * freq;
    float sn, cs;
    sincosf(ang, &sn, &cs);

    long base = (long)bs * EMB + h * HDIM + i;
    const float qscale = 0.08838834764831845f;

    float q1 = q[base], q2 = q[base + 64];
    q[base]      = (q1 * cs - q2 * sn) * qscale;
    q[base + 64] = (q2 * cs + q1 * sn) * qscale;

    float k1 = k[base], k2 = k[base + 64];
    k[base]      = k1 * cs - k2 * sn;
    k[base + 64] = k2 * cs + k1 * sn;
}

// ============================================================================
// Flash attention, causal. BM=BN=64, D=128, 256 threads (passing R1 version)
// ============================================================================
__global__ __launch_bounds__(256) void flash_kernel(const float* __restrict__ Q,
                                                    const float* __restrict__ K,
                                                    const float* __restrict__ V,
                                                    const float* __restrict__ mask,
                                                    float* __restrict__ ctx)
{
    extern __shared__ float sm[];
    float* Qs = sm;                 // [128][65]
    float* Ks = Qs + 128 * 65;      // [128][65]
    float* Vs = Ks + 128 * 65;      // [64][128]
    float* Ps = Vs + 64 * 128;      // [64][65]
    float* mv = Ps + 64 * 65;       // [64]

    const int tid = threadIdx.x;
    const int ty = tid >> 4, tx = tid & 15;
    const int r0 = ty * 4, c0 = tx * 4, co = tx * 8;
    const int q0 = blockIdx.x * 64;
    const int h  = blockIdx.y;
    const int b  = blockIdx.z;

    const float* Qg = Q + ((long)(b * SEQ + q0)) * EMB + h * HDIM;
    #pragma unroll
    for (int it = 0; it < 8; it++) {
        int id = tid + it * 256;
        int r  = id >> 5;
        int c4 = (id & 31) * 4;
        float4 v = *(const float4*)&Qg[(long)r * EMB + c4];
        Qs[(c4+0)*65 + r] = v.x; Qs[(c4+1)*65 + r] = v.y;
        Qs[(c4+2)*65 + r] = v.z; Qs[(c4+3)*65 + r] = v.w;
    }

    float O[4][8] = {};
    float m_i[4], l_i[4];
    #pragma unroll
    for (int i = 0; i < 4; i++) { m_i[i] = -INFINITY; l_i[i] = 0.f; }

    const int nkb = (q0 >> 6) + 1;
    for (int kb = 0; kb < nkb; kb++) {
        __syncthreads();
        const float* Kg = K + ((long)(b * SEQ + kb * 64)) * EMB + h * HDIM;
        const float* Vg = V + ((long)(b * SEQ + kb * 64)) * EMB + h * HDIM;
        #pragma unroll
        for (int it = 0; it < 8; it++) {
            int id = tid + it * 256;
            int r  = id >> 5;
            int c4 = (id & 31) * 4;
            float4 kv = *(const float4*)&Kg[(long)r * EMB + c4];
            Ks[(c4+0)*65 + r] = kv.x; Ks[(c4+1)*65 + r] = kv.y;
            Ks[(c4+2)*65 + r] = kv.z; Ks[(c4+3)*65 + r] = kv.w;
            float4 vv = *(const float4*)&Vg[(long)r * EMB + c4];
            *(float4*)&Vs[r * 128 + c4] = vv;
        }
        if (tid < 64) mv[tid] = (1.0f - mask[b * SEQ + kb * 64 + tid]) * -1e9f;
        __syncthreads();

        float s[4][4] = {};
        #pragma unroll 4
        for (int kk = 0; kk < 128; kk++) {
            float a[4], bb[4];
            #pragma unroll
            for (int i = 0; i < 4; i++) a[i]  = Qs[kk * 65 + r0 + i];
            #pragma unroll
            for (int j = 0; j < 4; j++) bb[j] = Ks[kk * 65 + c0 + j];
            #pragma unroll
            for (int i = 0; i < 4; i++)
                #pragma unroll
                for (int j = 0; j < 4; j++)
                    s[i][j] = fmaf(a[i], bb[j], s[i][j]);
        }

        #pragma unroll
        for (int i = 0; i < 4; i++)
            #pragma unroll
            for (int j = 0; j < 4; j++)
                s[i][j] += mv[c0 + j];
        if (kb == nkb - 1) {
            #pragma unroll
            for (int i = 0; i < 4; i++)
                #pragma unroll
                for (int j = 0; j < 4; j++)
                    if (kb * 64 + c0 + j > q0 + r0 + i) s[i][j] = -INFINITY;
        }

        float alpha[4];
        #pragma unroll
        for (int i = 0; i < 4; i++) {
            float rm = fmaxf(fmaxf(s[i][0], s[i][1]), fmaxf(s[i][2], s[i][3]));
            #pragma unroll
            for (int o = 1; o < 16; o <<= 1)
                rm = fmaxf(rm, __shfl_xor_sync(0xffffffffu, rm, o));
            float mnew = fmaxf(m_i[i], rm);
            alpha[i] = exp2f((m_i[i] - mnew) * LOG2E);
            m_i[i] = mnew;
        }
        #pragma unroll
        for (int i = 0; i < 4; i++) {
            float rs = 0.f;
            #pragma unroll
            for (int j = 0; j < 4; j++) {
                float pv = exp2f((s[i][j] - m_i[i]) * LOG2E);
                s[i][j] = pv;
                rs += pv;
            }
            #pragma unroll
            for (int o = 1; o < 16; o <<= 1)
                rs += __shfl_xor_sync(0xffffffffu, rs, o);
            l_i[i] = l_i[i] * alpha[i] + rs;
            #pragma unroll
            for (int jj = 0; jj < 8; jj++) O[i][jj] *= alpha[i];
        }

        #pragma unroll
        for (int i = 0; i < 4; i++)
            #pragma unroll
            for (int j = 0; j < 4; j++)
                Ps[(c0 + j) * 65 + (r0 + i)] = s[i][j];
        __syncthreads();

        #pragma unroll 2
        for (int j = 0; j < 64; j++) {
            float a2[4];
            #pragma unroll
            for (int i = 0; i < 4; i++) a2[i] = Ps[j * 65 + r0 + i];
            float4 v0 = *(const float4*)&Vs[j * 128 + co];
            float4 v1 = *(const float4*)&Vs[j * 128 + co + 4];
            #pragma unroll
            for (int i = 0; i < 4; i++) {
                O[i][0] = fmaf(a2[i], v0.x, O[i][0]);
                O[i][1] = fmaf(a2[i], v0.y, O[i][1]);
                O[i][2] = fmaf(a2[i], v0.z, O[i][2]);
                O[i][3] = fmaf(a2[i], v0.w, O[i][3]);
                O[i][4] = fmaf(a2[i], v1.x, O[i][4]);
                O[i][5] = fmaf(a2[i], v1.y, O[i][5]);
                O[i][6] = fmaf(a2[i], v1.z, O[i][6]);
                O[i][7] = fmaf(a2[i], v1.w, O[i][7]);
            }
        }
    }

    float* Og = ctx + ((long)(b * SEQ + q0)) * EMB + h * HDIM;
    #pragma unroll
    for (int i = 0; i < 4; i++) {
        float inv = 1.0f / l_i[i];
        float4 o0 = make_float4(O[i][0]*inv, O[i][1]*inv, O[i][2]*inv, O[i][3]*inv);
        float4 o1 = make_float4(O[i][4]*inv, O[i][5]*inv, O[i][6]*inv, O[i][7]*inv);
        *(float4*)&Og[(long)(r0 + i) * EMB + co]     = o0;
        *(float4*)&Og[(long)(r0 + i) * EMB + co + 4] = o1;
    }
}

// ============================================================================
// launch
// ============================================================================
extern "C" void kernel_launch(void* const* d_in, const int* in_sizes, int n_in,
                              void* d_out, int out_size)
{
    const float* x    = (const float*)d_in[0];
    const float* mask = (const float*)d_in[1];
    const float* Wq   = (const float*)d_in[2];
    const float* Wk   = (const float*)d_in[3];
    const float* Wv   = (const float*)d_in[4];
    const float* Wo   = (const float*)d_in[5];
    float* out = (float*)d_out;

    float *qp, *kp, *vp, *cxp;
    __nv_bfloat16 *axp, *wqp, *wkp, *wvp, *wop;
    cudaGetSymbolAddress((void**)&qp, g_Q);
    cudaGetSymbolAddress((void**)&kp, g_K);
    cudaGetSymbolAddress((void**)&vp, g_V);
    cudaGetSymbolAddress((void**)&cxp, g_ctx);
    cudaGetSymbolAddress((void**)&axp, g_Ax);
    cudaGetSymbolAddress((void**)&wqp, g_Wqs);
    cudaGetSymbolAddress((void**)&wkp, g_Wks);
    cudaGetSymbolAddress((void**)&wvp, g_Wvs);
    cudaGetSymbolAddress((void**)&wop, g_Wos);

    split_bf16<<<(MTOT * 512) / 256, 256>>>(x,  axp, 1);
    split_bf16<<<(EMB  * 512) / 256, 256>>>(Wq, wqp, 0);
    split_bf16<<<(EMB  * 512) / 256, 256>>>(Wk, wkp, 0);
    split_bf16<<<(EMB  * 512) / 256, 256>>>(Wv, wvp, 0);
    split_bf16<<<(EMB  * 512) / 256, 256>>>(Wo, wop, 0);

    cudaFuncSetAttribute(gemm_bf16s, cudaFuncAttributeMaxDynamicSharedMemorySize, G_SMEM);
    dim3 gg(EMB / 128, MTOT / 128);
    gemm_bf16s<<<gg, 256, G_SMEM>>>(axp, wqp, qp, EMB);
    gemm_bf16s<<<gg, 256, G_SMEM>>>(axp, wkp, kp, EMB);
    gemm_bf16s<<<gg, 256, G_SMEM>>>(axp, wvp, vp, EMB);

    rope_kernel<<<(MTOT * 1024) / 256, 256>>>(qp, kp);

    const int smem_bytes = (128*65 + 128*65 + 64*128 + 64*65 + 64) * 4;
    cudaFuncSetAttribute(flash_kernel, cudaFuncAttributeMaxDynamicSharedMemorySize,
                         smem_bytes);
    flash_kernel<<<dim3(SEQ / 64, NHEAD, BATCH), 256, smem_bytes>>>(qp, kp, vp, mask, cxp);

    split_bf16<<<(MTOT * 512) / 256, 256>>>(cxp, axp, 1);
    gemm_bf16s<<<gg, 256, G_SMEM>>>(axp, wop, out, EMB);
}

// round 4
// speedup vs baseline: 2.5640x; 1.6623x over previous
#include <cuda_runtime.h>
#include <cuda_bf16.h>
#include <cuda_fp16.h>
#include <math.h>
#include <cstdint>

#define BATCH 2
#define SEQ   2048
#define EMB   2048
#define NHEAD 16
#define HDIM  128
#define MTOT  (BATCH*SEQ)   // 4096
#define KP    (3*EMB)       // 6144 (tripled K for bf16 3-term split)
#define LOG2E 1.4426950408889634f

// ---- scratch (static device allocations) ----
__device__ float g_Q[MTOT*EMB];
__device__ float g_K[MTOT*EMB];
__device__ float g_V[MTOT*EMB];
__device__ float g_ctx[MTOT*EMB];
__device__ __half g_Qh[MTOT*EMB];
__device__ __half g_Kh[MTOT*EMB];
__device__ __half g_Vh[MTOT*EMB];
__device__ __nv_bfloat16 g_Ax[(size_t)MTOT*KP];
__device__ __nv_bfloat16 g_Wqs[(size_t)EMB*KP];
__device__ __nv_bfloat16 g_Wks[(size_t)EMB*KP];
__device__ __nv_bfloat16 g_Wvs[(size_t)EMB*KP];
__device__ __nv_bfloat16 g_Wos[(size_t)EMB*KP];

// ============================================================================
// helpers
// ============================================================================
__device__ __forceinline__ uint32_t smem_u32(const void* p) {
    uint32_t a;
    asm("{ .reg .u64 t; cvta.to.shared.u64 t, %1; cvt.u32.u64 %0, t; }"
        : "=r"(a) : "l"(p));
    return a;
}
__device__ __forceinline__ void cp16(uint32_t dst, const void* src) {
    asm volatile("cp.async.cg.shared.global [%0], [%1], 16;\n" :: "r"(dst), "l"(src));
}
#define CP_COMMIT() asm volatile("cp.async.commit_group;" ::: "memory")
#define CP_WAIT(n)  asm volatile("cp.async.wait_group %0;" :: "n"(n) : "memory")

__device__ __forceinline__ void ldsm_x4(uint32_t (&r)[4], uint32_t addr) {
    asm volatile("ldmatrix.sync.aligned.m8n8.x4.shared.b16 {%0,%1,%2,%3}, [%4];"
                 : "=r"(r[0]), "=r"(r[1]), "=r"(r[2]), "=r"(r[3]) : "r"(addr));
}
__device__ __forceinline__ void ldsm_x2(uint32_t (&r)[2], uint32_t addr) {
    asm volatile("ldmatrix.sync.aligned.m8n8.x2.shared.b16 {%0,%1}, [%2];"
                 : "=r"(r[0]), "=r"(r[1]) : "r"(addr));
}
__device__ __forceinline__ void ldsm_x2t(uint32_t (&r)[2], uint32_t addr) {
    asm volatile("ldmatrix.sync.aligned.m8n8.x2.trans.shared.b16 {%0,%1}, [%2];"
                 : "=r"(r[0]), "=r"(r[1]) : "r"(addr));
}
__device__ __forceinline__ void mma_bf16(float (&d)[4], const uint32_t (&a)[4],
                                         const uint32_t (&b)[2]) {
    asm volatile(
        "mma.sync.aligned.m16n8k16.row.col.f32.bf16.bf16.f32 "
        "{%0,%1,%2,%3}, {%4,%5,%6,%7}, {%8,%9}, {%0,%1,%2,%3};"
        : "+f"(d[0]), "+f"(d[1]), "+f"(d[2]), "+f"(d[3])
        : "r"(a[0]), "r"(a[1]), "r"(a[2]), "r"(a[3]), "r"(b[0]), "r"(b[1]));
}
__device__ __forceinline__ void mma_f16(float (&d)[4], const uint32_t (&a)[4],
                                        const uint32_t (&b)[2]) {
    asm volatile(
        "mma.sync.aligned.m16n8k16.row.col.f32.f16.f16.f32 "
        "{%0,%1,%2,%3}, {%4,%5,%6,%7}, {%8,%9}, {%0,%1,%2,%3};"
        : "+f"(d[0]), "+f"(d[1]), "+f"(d[2]), "+f"(d[3])
        : "r"(a[0]), "r"(a[1]), "r"(a[2]), "r"(a[3]), "r"(b[0]), "r"(b[1]));
}
__device__ __forceinline__ float fexp2(float x) {
    float y;
    asm("ex2.approx.ftz.f32 %0, %1;" : "=f"(y) : "f"(x));
    return y;
}
__device__ __forceinline__ uint32_t pack_h2(float a, float b) {
    __half2 h = __floats2half2_rn(a, b);
    return *(uint32_t*)&h;
}

// ============================================================================
// split: fp32 [R,2048] -> bf16 [R,6144]; A-pattern [hi,lo,hi], B-pattern [hi,hi,lo]
// ============================================================================
__global__ void split_bf16(const float* __restrict__ in, __nv_bfloat16* __restrict__ out,
                           int aPattern)
{
    int idx = blockIdx.x * blockDim.x + threadIdx.x;
    int r = idx >> 9;
    int c = (idx & 511) << 2;
    float4 v = *(const float4*)&in[((size_t)r << 11) + c];
    __nv_bfloat162 h01 = __floats2bfloat162_rn(v.x, v.y);
    __nv_bfloat162 h23 = __floats2bfloat162_rn(v.z, v.w);
    float2 f01 = __bfloat1622float2(h01);
    float2 f23 = __bfloat1622float2(h23);
    __nv_bfloat162 l01 = __floats2bfloat162_rn(v.x - f01.x, v.y - f01.y);
    __nv_bfloat162 l23 = __floats2bfloat162_rn(v.z - f23.x, v.w - f23.y);
    uint2 H, L;
    H.x = *(uint32_t*)&h01; H.y = *(uint32_t*)&h23;
    L.x = *(uint32_t*)&l01; L.y = *(uint32_t*)&l23;
    size_t ob = (size_t)r * KP + c;
    *(uint2*)&out[ob] = H;
    *(uint2*)&out[ob + 2048] = aPattern ? L : H;
    *(uint2*)&out[ob + 4096] = aPattern ? H : L;
}

// ============================================================================
// HMMA bf16 GEMM (unchanged from R3, passing): C = A'[M,KP] * B'[N,KP]^T
// ============================================================================
#define BKG       32
#define GSTRIDE   40
#define TILE_B    (128 * GSTRIDE * 2)
#define STAGE_B   (2 * TILE_B)
#define G_NCH     (KP / BKG)
#define G_SMEM    (3 * STAGE_B)

__device__ __forceinline__ void g_load_stage(uint32_t sbase,
                                             const __nv_bfloat16* __restrict__ A,
                                             const __nv_bfloat16* __restrict__ B,
                                             int m0, int n0, int c, int tid)
{
    const __nv_bfloat16* Ag = A + (size_t)m0 * KP + c * BKG;
    const __nv_bfloat16* Bg = B + (size_t)n0 * KP + c * BKG;
    #pragma unroll
    for (int i = 0; i < 2; i++) {
        int id = tid + i * 256;
        int r  = id >> 2;
        int ch = id & 3;
        cp16(sbase + r * 80 + ch * 16, Ag + (size_t)r * KP + ch * 8);
        cp16(sbase + TILE_B + r * 80 + ch * 16, Bg + (size_t)r * KP + ch * 8);
    }
}

__global__ __launch_bounds__(256) void gemm_bf16s(const __nv_bfloat16* __restrict__ A,
                                                  const __nv_bfloat16* __restrict__ B,
                                                  float* __restrict__ C, int N)
{
    extern __shared__ __align__(128) char smem[];
    const uint32_t sb = smem_u32(smem);
    const int tid  = threadIdx.x;
    const int lane = tid & 31;
    const int w    = tid >> 5;
    const int wr   = w >> 1;
    const int wc   = w & 1;
    const int m0 = blockIdx.y * 128;
    const int n0 = blockIdx.x * 128;

    float acc[2][8][4] = {};

    const uint32_t aoff = (uint32_t)((wr * 32 + (lane & 15)) * GSTRIDE + (lane >> 4) * 8) * 2;
    const uint32_t boff = TILE_B +
        (uint32_t)((wc * 64 + (lane & 7)) * GSTRIDE + ((lane >> 3) & 1) * 8) * 2;

    g_load_stage(sb, A, B, m0, n0, 0, tid);
    CP_COMMIT();
    g_load_stage(sb + STAGE_B, A, B, m0, n0, 1, tid);
    CP_COMMIT();

    for (int c = 0; c < G_NCH; c++) {
        if (c == G_NCH - 1) { CP_WAIT(0); } else { CP_WAIT(1); }
        __syncthreads();

        const int cn = c + 2;
        if (cn < G_NCH) {
            g_load_stage(sb + (cn % 3) * STAGE_B, A, B, m0, n0, cn, tid);
            CP_COMMIT();
        }

        const uint32_t stg = sb + (c % 3) * STAGE_B;
        #pragma unroll
        for (int ks = 0; ks < 2; ks++) {
            uint32_t af[2][4];
            #pragma unroll
            for (int mt = 0; mt < 2; mt++)
                ldsm_x4(af[mt], stg + aoff + (uint32_t)(mt * 16 * GSTRIDE + ks * 16) * 2);
            uint32_t bf[8][2];
            #pragma unroll
            for (int nt = 0; nt < 8; nt++)
                ldsm_x2(bf[nt], stg + boff + (uint32_t)(nt * 8 * GSTRIDE + ks * 16) * 2);
            #pragma unroll
            for (int mt = 0; mt < 2; mt++)
                #pragma unroll
                for (int nt = 0; nt < 8; nt++)
                    mma_bf16(acc[mt][nt], af[mt], bf[nt]);
        }
        __syncthreads();
    }

    const int r0 = m0 + wr * 32 + (lane >> 2);
    const int c0 = n0 + wc * 64 + (lane & 3) * 2;
    #pragma unroll
    for (int mt = 0; mt < 2; mt++)
        #pragma unroll
        for (int nt = 0; nt < 8; nt++) {
            float* p0 = &C[(size_t)(r0 + mt * 16) * N + c0 + nt * 8];
            float* p1 = &C[(size_t)(r0 + mt * 16 + 8) * N + c0 + nt * 8];
            *(float2*)p0 = make_float2(acc[mt][nt][0], acc[mt][nt][1]);
            *(float2*)p1 = make_float2(acc[mt][nt][2], acc[mt][nt][3]);
        }
}

// ============================================================================
// RoPE -> fp16: reads fp32 q,k; writes fp16. Q gets LOG2E/sqrt(128) folded in.
// ============================================================================
__global__ void rope_half(const float* __restrict__ q, const float* __restrict__ k,
                          __half* __restrict__ qh, __half* __restrict__ kh)
{
    int idx = blockIdx.x * blockDim.x + threadIdx.x;
    int p  = idx & 1023;
    int bs = idx >> 10;
    int s  = bs & (SEQ - 1);
    int h  = p >> 6, i = p & 63;

    float freq = exp2f(-(float)i * 0.20762050593046010f);
    float ang  = (float)s * freq;
    float sn, cs;
    sincosf(ang, &sn, &cs);

    long base = (long)bs * EMB + h * HDIM + i;
    const float qs = 1.4426950408889634f * 0.08838834764831845f;  // log2e/sqrt(128)

    float q1 = q[base], q2 = q[base + 64];
    qh[base]      = __float2half((q1 * cs - q2 * sn) * qs);
    qh[base + 64] = __float2half((q2 * cs + q1 * sn) * qs);

    float k1 = k[base], k2 = k[base + 64];
    kh[base]      = __float2half(k1 * cs - k2 * sn);
    kh[base + 64] = __float2half(k2 * cs + k1 * sn);
}

__global__ void v_half(const float* __restrict__ v, __half* __restrict__ vh)
{
    int idx = blockIdx.x * blockDim.x + threadIdx.x;   // one float4 per thread
    float4 a = ((const float4*)v)[idx];
    __half2 h0 = __floats2half2_rn(a.x, a.y);
    __half2 h1 = __floats2half2_rn(a.z, a.w);
    uint2 o;
    o.x = *(uint32_t*)&h0; o.y = *(uint32_t*)&h1;
    ((uint2*)vh)[idx] = o;
}

// ============================================================================
// Flash attention, fp16 HMMA. BM=128, BN=64, 8 warps x 16 rows, 256 threads.
// K/V double-buffered cp.async. Smem rows padded to 272B (conflict-free ldsm).
// ============================================================================
#define FSTR  136
#define FSTRB 272
#define FQB   (128 * FSTRB)           // 34816
#define FKV   (2 * 64 * FSTRB)        // 34816 per stage (K then V)
#define FMV   (FQB + 2 * FKV)         // 104448
#define FSMEM (FMV + 512)             // 104960

__device__ __forceinline__ void f_load_kv(uint32_t stbase, const __half* __restrict__ Kg,
                                          const __half* __restrict__ Vg, int tid)
{
    #pragma unroll
    for (int i = 0; i < 4; i++) {
        int id = tid + i * 256;          // 0..1023
        int r  = id >> 4;                // 0..63
        int ch = id & 15;                // 16B chunk
        cp16(stbase + r * FSTRB + ch * 16, Kg + (size_t)r * EMB + ch * 8);
        cp16(stbase + 64 * FSTRB + r * FSTRB + ch * 16, Vg + (size_t)r * EMB + ch * 8);
    }
}

__global__ __launch_bounds__(256, 1) void flash_hmma(const __half* __restrict__ Qh,
                                                     const __half* __restrict__ Kh,
                                                     const __half* __restrict__ Vh,
                                                     const float* __restrict__ mask,
                                                     float* __restrict__ ctx)
{
    extern __shared__ __align__(128) char smem[];
    const uint32_t sb = smem_u32(smem);
    float* mvb = (float*)(smem + FMV);

    const int tid  = threadIdx.x;
    const int lane = tid & 31;
    const int w    = tid >> 5;
    const int q0 = blockIdx.x * 128;
    const int h  = blockIdx.y;
    const int b  = blockIdx.z;

    // load Q tile (128 rows x 256B)
    const __half* Qg = Qh + ((size_t)(b * SEQ + q0)) * EMB + h * HDIM;
    #pragma unroll
    for (int i = 0; i < 8; i++) {
        int id = tid + i * 256;          // 0..2047
        int r  = id >> 4;
        int ch = id & 15;
        cp16(sb + r * FSTRB + ch * 16, Qg + (size_t)r * EMB + ch * 8);
    }
    CP_COMMIT();

    const int nkb = (q0 >> 6) + 2;
    // prefetch KV block 0
    f_load_kv(sb + FQB, Kh + ((size_t)(b * SEQ)) * EMB + h * HDIM,
              Vh + ((size_t)(b * SEQ)) * EMB + h * HDIM, tid);
    CP_COMMIT();
    if (tid < 64) mvb[tid] = (1.0f - mask[b * SEQ + tid]) * -1.4426950e9f;

    float oacc[16][4] = {};
    float m_a = -INFINITY, m_b = -INFINITY, l_a = 0.f, l_b = 0.f;

    const uint32_t aqb = sb + (uint32_t)((w * 16 + (lane & 15)) * FSTRB + (lane >> 4) * 16);

    for (int kb = 0; kb < nkb; kb++) {
        const int st = kb & 1;
        const int kn = kb + 1;
        if (kn < nkb) {
            const int st2 = kn & 1;
            f_load_kv(sb + FQB + st2 * FKV,
                      Kh + ((size_t)(b * SEQ + kn * 64)) * EMB + h * HDIM,
                      Vh + ((size_t)(b * SEQ + kn * 64)) * EMB + h * HDIM, tid);
            CP_COMMIT();
            if (tid < 64)
                mvb[st2 * 64 + tid] = (1.0f - mask[b * SEQ + kn * 64 + tid]) * -1.4426950e9f;
            CP_WAIT(1);
        } else {
            CP_WAIT(0);
        }
        __syncthreads();

        const uint32_t kbase = sb + FQB + st * FKV;
        const uint32_t vbase = kbase + 64 * FSTRB;
        const float* mvp = mvb + st * 64;

        // ---- S = Q K^T ----
        float sacc[8][4] = {};
        const uint32_t bkb = kbase + (uint32_t)((lane & 7) * FSTRB + ((lane >> 3) & 1) * 16);
        #pragma unroll
        for (int ks = 0; ks < 8; ks++) {
            uint32_t aq[4];
            ldsm_x4(aq, aqb + ks * 32);
            #pragma unroll
            for (int nt = 0; nt < 8; nt++) {
                uint32_t bk[2];
                ldsm_x2(bk, bkb + (uint32_t)(nt * 8 * FSTRB) + ks * 32);
                mma_f16(sacc[nt], aq, bk);
            }
        }

        // ---- padding mask ----
        #pragma unroll
        for (int nt = 0; nt < 8; nt++) {
            float m0v = mvp[nt * 8 + (lane & 3) * 2];
            float m1v = mvp[nt * 8 + (lane & 3) * 2 + 1];
            sacc[nt][0] += m0v; sacc[nt][1] += m1v;
            sacc[nt][2] += m0v; sacc[nt][3] += m1v;
        }
        // ---- causal mask (diagonal-region blocks only) ----
        const int rowa = q0 + w * 16 + (lane >> 2);
        if (kb * 64 + 63 > q0 + w * 16) {
            #pragma unroll
            for (int nt = 0; nt < 8; nt++) {
                int col = kb * 64 + nt * 8 + (lane & 3) * 2;
                #pragma unroll
                for (int j = 0; j < 2; j++) {
                    if (col + j > rowa)     sacc[nt][j]     = -INFINITY;
                    if (col + j > rowa + 8) sacc[nt][j + 2] = -INFINITY;
                }
            }
        }

        // ---- online softmax (log2 domain; scale folded into Q) ----
        float rma = -INFINITY, rmb = -INFINITY;
        #pragma unroll
        for (int nt = 0; nt < 8; nt++) {
            rma = fmaxf(rma, fmaxf(sacc[nt][0], sacc[nt][1]));
            rmb = fmaxf(rmb, fmaxf(sacc[nt][2], sacc[nt][3]));
        }
        #pragma unroll
        for (int o = 1; o < 4; o <<= 1) {
            rma = fmaxf(rma, __shfl_xor_sync(0xffffffffu, rma, o));
            rmb = fmaxf(rmb, __shfl_xor_sync(0xffffffffu, rmb, o));
        }
        float mna = fmaxf(m_a, rma), mnb = fmaxf(m_b, rmb);
        float ala = fexp2(m_a - mna), alb = fexp2(m_b - mnb);
        m_a = mna; m_b = mnb;

        float sa = 0.f, sbm = 0.f;
        #pragma unroll
        for (int nt = 0; nt < 8; nt++) {
            sacc[nt][0] = fexp2(sacc[nt][0] - m_a);
            sacc[nt][1] = fexp2(sacc[nt][1] - m_a);
            sacc[nt][2] = fexp2(sacc[nt][2] - m_b);
            sacc[nt][3] = fexp2(sacc[nt][3] - m_b);
            sa  += sacc[nt][0] + sacc[nt][1];
            sbm += sacc[nt][2] + sacc[nt][3];
        }
        l_a = l_a * ala + sa;
        l_b = l_b * alb + sbm;
        #pragma unroll
        for (int nt2 = 0; nt2 < 16; nt2++) {
            oacc[nt2][0] *= ala; oacc[nt2][1] *= ala;
            oacc[nt2][2] *= alb; oacc[nt2][3] *= alb;
        }

        // ---- pack P to fp16 A-fragments ----
        uint32_t pA[4][4];
        #pragma unroll
        for (int kt = 0; kt < 4; kt++) {
            pA[kt][0] = pack_h2(sacc[2*kt][0],   sacc[2*kt][1]);
            pA[kt][1] = pack_h2(sacc[2*kt][2],   sacc[2*kt][3]);
            pA[kt][2] = pack_h2(sacc[2*kt+1][0], sacc[2*kt+1][1]);
            pA[kt][3] = pack_h2(sacc[2*kt+1][2], sacc[2*kt+1][3]);
        }

        // ---- O += P V ----
        const uint32_t bvb = vbase + (uint32_t)((lane & 15) * FSTRB);
        #pragma unroll
        for (int kt = 0; kt < 4; kt++) {
            #pragma unroll
            for (int nt2 = 0; nt2 < 16; nt2++) {
                uint32_t bv[2];
                ldsm_x2t(bv, bvb + (uint32_t)(kt * 16 * FSTRB) + nt2 * 16);
                mma_f16(oacc[nt2], pA[kt], bv);
            }
        }
        __syncthreads();
    }

    // final l reduce across the 4-thread row group
    #pragma unroll
    for (int o = 1; o < 4; o <<= 1) {
        l_a += __shfl_xor_sync(0xffffffffu, l_a, o);
        l_b += __shfl_xor_sync(0xffffffffu, l_b, o);
    }
    const float inva = 1.0f / l_a, invb = 1.0f / l_b;

    const int ra = q0 + w * 16 + (lane >> 2);
    float* Oa = ctx + ((size_t)(b * SEQ + ra)) * EMB + h * HDIM + (lane & 3) * 2;
    float* Ob = ctx + ((size_t)(b * SEQ + ra + 8)) * EMB + h * HDIM + (lane & 3) * 2;
    #pragma unroll
    for (int nt2 = 0; nt2 < 16; nt2++) {
        *(float2*)(Oa + nt2 * 8) = make_float2(oacc[nt2][0] * inva, oacc[nt2][1] * inva);
        *(float2*)(Ob + nt2 * 8) = make_float2(oacc[nt2][2] * invb, oacc[nt2][3] * invb);
    }
}

// ============================================================================
// launch
// ============================================================================
extern "C" void kernel_launch(void* const* d_in, const int* in_sizes, int n_in,
                              void* d_out, int out_size)
{
    const float* x    = (const float*)d_in[0];
    const float* mask = (const float*)d_in[1];
    const float* Wq   = (const float*)d_in[2];
    const float* Wk   = (const float*)d_in[3];
    const float* Wv   = (const float*)d_in[4];
    const float* Wo   = (const float*)d_in[5];
    float* out = (float*)d_out;

    float *qp, *kp, *vp, *cxp;
    __half *qhp, *khp, *vhp;
    __nv_bfloat16 *axp, *wqp, *wkp, *wvp, *wop;
    cudaGetSymbolAddress((void**)&qp, g_Q);
    cudaGetSymbolAddress((void**)&kp, g_K);
    cudaGetSymbolAddress((void**)&vp, g_V);
    cudaGetSymbolAddress((void**)&cxp, g_ctx);
    cudaGetSymbolAddress((void**)&qhp, g_Qh);
    cudaGetSymbolAddress((void**)&khp, g_Kh);
    cudaGetSymbolAddress((void**)&vhp, g_Vh);
    cudaGetSymbolAddress((void**)&axp, g_Ax);
    cudaGetSymbolAddress((void**)&wqp, g_Wqs);
    cudaGetSymbolAddress((void**)&wkp, g_Wks);
    cudaGetSymbolAddress((void**)&wvp, g_Wvs);
    cudaGetSymbolAddress((void**)&wop, g_Wos);

    split_bf16<<<(MTOT * 512) / 256, 256>>>(x,  axp, 1);
    split_bf16<<<(EMB  * 512) / 256, 256>>>(Wq, wqp, 0);
    split_bf16<<<(EMB  * 512) / 256, 256>>>(Wk, wkp, 0);
    split_bf16<<<(EMB  * 512) / 256, 256>>>(Wv, wvp, 0);
    split_bf16<<<(EMB  * 512) / 256, 256>>>(Wo, wop, 0);

    cudaFuncSetAttribute(gemm_bf16s, cudaFuncAttributeMaxDynamicSharedMemorySize, G_SMEM);
    dim3 gg(EMB / 128, MTOT / 128);
    gemm_bf16s<<<gg, 256, G_SMEM>>>(axp, wqp, qp, EMB);
    gemm_bf16s<<<gg, 256, G_SMEM>>>(axp, wkp, kp, EMB);
    gemm_bf16s<<<gg, 256, G_SMEM>>>(axp, wvp, vp, EMB);

    rope_half<<<(MTOT * 1024) / 256, 256>>>(qp, kp, qhp, khp);
    v_half<<<(MTOT * EMB / 4) / 256, 256>>>(vp, vhp);

    cudaFuncSetAttribute(flash_hmma, cudaFuncAttributeMaxDynamicSharedMemorySize, FSMEM);
    flash_hmma<<<dim3(SEQ / 128, NHEAD, BATCH), 256, FSMEM>>>(qhp, khp, vhp, mask, cxp);

    split_bf16<<<(MTOT * 512) / 256, 256>>>(cxp, axp, 1);
    gemm_bf16s<<<gg, 256, G_SMEM>>>(axp, wop, out, EMB);
}

// round 9
// speedup vs baseline: 3.8383x; 1.4970x over previous
#include <cuda_runtime.h>
#include <cuda_fp16.h>
#include <math.h>
#include <cstdint>

#define BATCH 2
#define SEQ   2048
#define EMB   2048
#define NHEAD 16
#define HDIM  128
#define MTOT  (BATCH*SEQ)   // 4096
#define KP2   4096          // doubled K for fp16 2-term split
#define LOG2E 1.4426950408889634f

// ---- scratch (static device allocations) ----
__device__ float  g_QKV[(size_t)MTOT*3*EMB];   // fused QKV GEMM output (fp32)
__device__ float  g_ctx[MTOT*EMB];
__device__ __half g_Qh[MTOT*EMB];
__device__ __half g_Kh[MTOT*EMB];
__device__ __half g_Vh[MTOT*EMB];
__device__ __half g_Ax[(size_t)MTOT*KP2];      // split x / split ctx (reused)
__device__ __half g_Wqkv[(size_t)3*EMB*KP2];   // [Wq;Wk;Wv] rows, split cols
__device__ __half g_Wos[(size_t)EMB*KP2];

// ============================================================================
// helpers
// ============================================================================
__device__ __forceinline__ uint32_t smem_u32(const void* p) {
    uint32_t a;
    asm("{ .reg .u64 t; cvta.to.shared.u64 t, %1; cvt.u32.u64 %0, t; }"
        : "=r"(a) : "l"(p));
    return a;
}
__device__ __forceinline__ void cp16(uint32_t dst, const void* src) {
    asm volatile("cp.async.cg.shared.global [%0], [%1], 16;\n" :: "r"(dst), "l"(src));
}
#define CP_COMMIT() asm volatile("cp.async.commit_group;" ::: "memory")
#define CP_WAIT(n)  asm volatile("cp.async.wait_group %0;" :: "n"(n) : "memory")

__device__ __forceinline__ void ldsm_x4(uint32_t (&r)[4], uint32_t addr) {
    asm volatile("ldmatrix.sync.aligned.m8n8.x4.shared.b16 {%0,%1,%2,%3}, [%4];"
                 : "=r"(r[0]), "=r"(r[1]), "=r"(r[2]), "=r"(r[3]) : "r"(addr));
}
__device__ __forceinline__ void ldsm_x2(uint32_t (&r)[2], uint32_t addr) {
    asm volatile("ldmatrix.sync.aligned.m8n8.x2.shared.b16 {%0,%1}, [%2];"
                 : "=r"(r[0]), "=r"(r[1]) : "r"(addr));
}
__device__ __forceinline__ void ldsm_x2t(uint32_t (&r)[2], uint32_t addr) {
    asm volatile("ldmatrix.sync.aligned.m8n8.x2.trans.shared.b16 {%0,%1}, [%2];"
                 : "=r"(r[0]), "=r"(r[1]) : "r"(addr));
}
__device__ __forceinline__ void mma_f16(float (&d)[4], const uint32_t (&a)[4],
                                        const uint32_t (&b)[2]) {
    asm volatile(
        "mma.sync.aligned.m16n8k16.row.col.f32.f16.f16.f32 "
        "{%0,%1,%2,%3}, {%4,%5,%6,%7}, {%8,%9}, {%0,%1,%2,%3};"
        : "+f"(d[0]), "+f"(d[1]), "+f"(d[2]), "+f"(d[3])
        : "r"(a[0]), "r"(a[1]), "r"(a[2]), "r"(a[3]), "r"(b[0]), "r"(b[1]));
}
__device__ __forceinline__ float fexp2(float x) {
    float y;
    asm("ex2.approx.ftz.f32 %0, %1;" : "=f"(y) : "f"(x));
    return y;
}
__device__ __forceinline__ uint32_t pack_h2(float a, float b) {
    __half2 h = __floats2half2_rn(a, b);
    return *(uint32_t*)&h;
}

// ============================================================================
// split: fp32 [R,2048] -> fp16 [R,4096]; A-pattern [hi,lo], B-pattern [hi,hi]
// ============================================================================
__global__ void split_f16(const float* __restrict__ in, __half* __restrict__ out,
                          int aPattern)
{
    int idx = blockIdx.x * blockDim.x + threadIdx.x;
    int r = idx >> 9;
    int c = (idx & 511) << 2;
    float4 v = *(const float4*)&in[((size_t)r << 11) + c];
    __half2 h01 = __floats2half2_rn(v.x, v.y);
    __half2 h23 = __floats2half2_rn(v.z, v.w);
    float2 f01 = __half22float2(h01);
    float2 f23 = __half22float2(h23);
    __half2 l01 = __floats2half2_rn(v.x - f01.x, v.y - f01.y);
    __half2 l23 = __floats2half2_rn(v.z - f23.x, v.w - f23.y);
    uint2 H, L;
    H.x = *(uint32_t*)&h01; H.y = *(uint32_t*)&h23;
    L.x = *(uint32_t*)&l01; L.y = *(uint32_t*)&l23;
    size_t ob = (size_t)r * KP2 + c;
    *(uint2*)&out[ob] = H;
    *(uint2*)&out[ob + 2048] = aPattern ? L : H;
}

// ============================================================================
// HMMA fp16 GEMM: C[M,N] fp32 = A'[M,KP2] * B'[N,KP2]^T (row-major, K contig)
// Tile 128x128, BK=32, 256 threads = 8 warps (4x2), warp tile 32x64,
// 3-stage cp.async ring, ONE barrier per chunk, padded smem rows (80B).
// ============================================================================
#define BKG       32
#define GSTRIDE   40
#define TILE_B    (128 * GSTRIDE * 2)
#define STAGE_B   (2 * TILE_B)
#define G_NCH     (KP2 / BKG)          // 128
#define G_SMEM    (3 * STAGE_B)        // 61440

__device__ __forceinline__ void g_load_stage(uint32_t sbase,
                                             const __half* __restrict__ A,
                                             const __half* __restrict__ B,
                                             int m0, int n0, int c, int tid)
{
    const __half* Ag = A + (size_t)m0 * KP2 + c * BKG;
    const __half* Bg = B + (size_t)n0 * KP2 + c * BKG;
    #pragma unroll
    for (int i = 0; i < 2; i++) {
        int id = tid + i * 256;
        int r  = id >> 2;
        int ch = id & 3;
        cp16(sbase + r * 80 + ch * 16, Ag + (size_t)r * KP2 + ch * 8);
        cp16(sbase + TILE_B + r * 80 + ch * 16, Bg + (size_t)r * KP2 + ch * 8);
    }
}

__global__ __launch_bounds__(256) void gemm_f16s(const __half* __restrict__ A,
                                                 const __half* __restrict__ B,
                                                 float* __restrict__ C, int N)
{
    extern __shared__ __align__(128) char smem[];
    const uint32_t sb = smem_u32(smem);
    const int tid  = threadIdx.x;
    const int lane = tid & 31;
    const int w    = tid >> 5;
    const int wr   = w >> 1;
    const int wc   = w & 1;
    const int m0 = blockIdx.y * 128;
    const int n0 = blockIdx.x * 128;

    float acc[2][8][4] = {};

    const uint32_t aoff = (uint32_t)((wr * 32 + (lane & 15)) * GSTRIDE + (lane >> 4) * 8) * 2;
    const uint32_t boff = TILE_B +
        (uint32_t)((wc * 64 + (lane & 7)) * GSTRIDE + ((lane >> 3) & 1) * 8) * 2;

    g_load_stage(sb, A, B, m0, n0, 0, tid);
    CP_COMMIT();
    g_load_stage(sb + STAGE_B, A, B, m0, n0, 1, tid);
    CP_COMMIT();

    for (int c = 0; c < G_NCH; c++) {
        if (c < G_NCH - 1) { CP_WAIT(1); } else { CP_WAIT(0); }
        __syncthreads();

        const int cn = c + 2;
        if (cn < G_NCH) {
            g_load_stage(sb + (cn % 3) * STAGE_B, A, B, m0, n0, cn, tid);
            CP_COMMIT();
        }

        const uint32_t stg = sb + (c % 3) * STAGE_B;
        #pragma unroll
        for (int ks = 0; ks < 2; ks++) {
            uint32_t af[2][4];
            #pragma unroll
            for (int mt = 0; mt < 2; mt++)
                ldsm_x4(af[mt], stg + aoff + (uint32_t)(mt * 16 * GSTRIDE + ks * 16) * 2);
            uint32_t bf[8][2];
            #pragma unroll
            for (int nt = 0; nt < 8; nt++)
                ldsm_x2(bf[nt], stg + boff + (uint32_t)(nt * 8 * GSTRIDE + ks * 16) * 2);
            #pragma unroll
            for (int mt = 0; mt < 2; mt++)
                #pragma unroll
                for (int nt = 0; nt < 8; nt++)
                    mma_f16(acc[mt][nt], af[mt], bf[nt]);
        }
    }

    const int r0 = m0 + wr * 32 + (lane >> 2);
    const int c0 = n0 + wc * 64 + (lane & 3) * 2;
    #pragma unroll
    for (int mt = 0; mt < 2; mt++)
        #pragma unroll
        for (int nt = 0; nt < 8; nt++) {
            float* p0 = &C[(size_t)(r0 + mt * 16) * N + c0 + nt * 8];
            float* p1 = &C[(size_t)(r0 + mt * 16 + 8) * N + c0 + nt * 8];
            *(float2*)p0 = make_float2(acc[mt][nt][0], acc[mt][nt][1]);
            *(float2*)p1 = make_float2(acc[mt][nt][2], acc[mt][nt][3]);
        }
}

// ============================================================================
// RoPE from fused QKV (stride 6144) -> fp16 Q,K. Q gets LOG2E/sqrt(128) folded.
// ============================================================================
__global__ void rope_half(const float* __restrict__ qkv,
                          __half* __restrict__ qh, __half* __restrict__ kh)
{
    int idx = blockIdx.x * blockDim.x + threadIdx.x;
    int p  = idx & 1023;
    int bs = idx >> 10;
    int s  = bs & (SEQ - 1);
    int h  = p >> 6, i = p & 63;

    float freq = exp2f(-(float)i * 0.20762050593046010f);
    float ang  = (float)s * freq;
    float sn, cs;
    sincosf(ang, &sn, &cs);

    size_t src = (size_t)bs * (3 * EMB) + h * HDIM + i;
    long   dst = (long)bs * EMB + h * HDIM + i;
    const float qs = 1.4426950408889634f * 0.08838834764831845f;

    float q1 = qkv[src],        q2 = qkv[src + 64];
    qh[dst]      = __float2half((q1 * cs - q2 * sn) * qs);
    qh[dst + 64] = __float2half((q2 * cs + q1 * sn) * qs);

    float k1 = qkv[src + 2048], k2 = qkv[src + 2048 + 64];
    kh[dst]      = __float2half(k1 * cs - k2 * sn);
    kh[dst + 64] = __float2half(k2 * cs + k1 * sn);
}

__global__ void v_half(const float* __restrict__ qkv, __half* __restrict__ vh)
{
    int idx = blockIdx.x * blockDim.x + threadIdx.x;   // one float4 per thread
    int r  = idx >> 9;
    int c4 = (idx & 511) << 2;
    const float* src = qkv + (size_t)r * (3 * EMB) + 4096 + c4;
    float4 a = *(const float4*)src;
    __half2 h0 = __floats2half2_rn(a.x, a.y);
    __half2 h1 = __floats2half2_rn(a.z, a.w);
    uint2 o;
    o.x = *(uint32_t*)&h0; o.y = *(uint32_t*)&h1;
    *(uint2*)&vh[(size_t)r * EMB + c4] = o;
}

// ============================================================================
// Flash attention, fp16 HMMA (passing R4 version). BM=128, BN=64, 256 thr.
// ============================================================================
#define FSTR  136
#define FSTRB 272
#define FQB   (128 * FSTRB)
#define FKV   (2 * 64 * FSTRB)
#define FMV   (FQB + 2 * FKV)
#define FSMEM (FMV + 512)

__device__ __forceinline__ void f_load_kv(uint32_t stbase, const __half* __restrict__ Kg,
                                          const __half* __restrict__ Vg, int tid)
{
    #pragma unroll
    for (int i = 0; i < 4; i++) {
        int id = tid + i * 256;
        int r  = id >> 4;
        int ch = id & 15;
        cp16(stbase + r * FSTRB + ch * 16, Kg + (size_t)r * EMB + ch * 8);
        cp16(stbase + 64 * FSTRB + r * FSTRB + ch * 16, Vg + (size_t)r * EMB + ch * 8);
    }
}

__global__ __launch_bounds__(256, 1) void flash_hmma(const __half* __restrict__ Qh,
                                                     const __half* __restrict__ Kh,
                                                     const __half* __restrict__ Vh,
                                                     const float* __restrict__ mask,
                                                     float* __restrict__ ctx)
{
    extern __shared__ __align__(128) char smem[];
    const uint32_t sb = smem_u32(smem);
    float* mvb = (float*)(smem + FMV);

    const int tid  = threadIdx.x;
    const int lane = tid & 31;
    const int w    = tid >> 5;
    const int q0 = blockIdx.x * 128;
    const int h  = blockIdx.y;
    const int b  = blockIdx.z;

    const __half* Qg = Qh + ((size_t)(b * SEQ + q0)) * EMB + h * HDIM;
    #pragma unroll
    for (int i = 0; i < 8; i++) {
        int id = tid + i * 256;
        int r  = id >> 4;
        int ch = id & 15;
        cp16(sb + r * FSTRB + ch * 16, Qg + (size_t)r * EMB + ch * 8);
    }
    CP_COMMIT();

    const int nkb = (q0 >> 6) + 2;
    f_load_kv(sb + FQB, Kh + ((size_t)(b * SEQ)) * EMB + h * HDIM,
              Vh + ((size_t)(b * SEQ)) * EMB + h * HDIM, tid);
    CP_COMMIT();
    if (tid < 64) mvb[tid] = (1.0f - mask[b * SEQ + tid]) * -1.4426950e9f;

    float oacc[16][4] = {};
    float m_a = -INFINITY, m_b = -INFINITY, l_a = 0.f, l_b = 0.f;

    const uint32_t aqb = sb + (uint32_t)((w * 16 + (lane & 15)) * FSTRB + (lane >> 4) * 16);

    for (int kb = 0; kb < nkb; kb++) {
        const int st = kb & 1;
        const int kn = kb + 1;
        if (kn < nkb) {
            const int st2 = kn & 1;
            f_load_kv(sb + FQB + st2 * FKV,
                      Kh + ((size_t)(b * SEQ + kn * 64)) * EMB + h * HDIM,
                      Vh + ((size_t)(b * SEQ + kn * 64)) * EMB + h * HDIM, tid);
            CP_COMMIT();
            if (tid < 64)
                mvb[st2 * 64 + tid] = (1.0f - mask[b * SEQ + kn * 64 + tid]) * -1.4426950e9f;
            CP_WAIT(1);
        } else {
            CP_WAIT(0);
        }
        __syncthreads();

        const uint32_t kbase = sb + FQB + st * FKV;
        const uint32_t vbase = kbase + 64 * FSTRB;
        const float* mvp = mvb + st * 64;

        float sacc[8][4] = {};
        const uint32_t bkb = kbase + (uint32_t)((lane & 7) * FSTRB + ((lane >> 3) & 1) * 16);
        #pragma unroll
        for (int ks = 0; ks < 8; ks++) {
            uint32_t aq[4];
            ldsm_x4(aq, aqb + ks * 32);
            #pragma unroll
            for (int nt = 0; nt < 8; nt++) {
                uint32_t bk[2];
                ldsm_x2(bk, bkb + (uint32_t)(nt * 8 * FSTRB) + ks * 32);
                mma_f16(sacc[nt], aq, bk);
            }
        }

        #pragma unroll
        for (int nt = 0; nt < 8; nt++) {
            float m0v = mvp[nt * 8 + (lane & 3) * 2];
            float m1v = mvp[nt * 8 + (lane & 3) * 2 + 1];
            sacc[nt][0] += m0v; sacc[nt][1] += m1v;
            sacc[nt][2] += m0v; sacc[nt][3] += m1v;
        }
        const int rowa = q0 + w * 16 + (lane >> 2);
        if (kb * 64 + 63 > q0 + w * 16) {
            #pragma unroll
            for (int nt = 0; nt < 8; nt++) {
                int col = kb * 64 + nt * 8 + (lane & 3) * 2;
                #pragma unroll
                for (int j = 0; j < 2; j++) {
                    if (col + j > rowa)     sacc[nt][j]     = -INFINITY;
                    if (col + j > rowa + 8) sacc[nt][j + 2] = -INFINITY;
                }
            }
        }

        float rma = -INFINITY, rmb = -INFINITY;
        #pragma unroll
        for (int nt = 0; nt < 8; nt++) {
            rma = fmaxf(rma, fmaxf(sacc[nt][0], sacc[nt][1]));
            rmb = fmaxf(rmb, fmaxf(sacc[nt][2], sacc[nt][3]));
        }
        #pragma unroll
        for (int o = 1; o < 4; o <<= 1) {
            rma = fmaxf(rma, __shfl_xor_sync(0xffffffffu, rma, o));
            rmb = fmaxf(rmb, __shfl_xor_sync(0xffffffffu, rmb, o));
        }
        float mna = fmaxf(m_a, rma), mnb = fmaxf(m_b, rmb);
        float ala = fexp2(m_a - mna), alb = fexp2(m_b - mnb);
        m_a = mna; m_b = mnb;

        float sa = 0.f, sbm = 0.f;
        #pragma unroll
        for (int nt = 0; nt < 8; nt++) {
            sacc[nt][0] = fexp2(sacc[nt][0] - m_a);
            sacc[nt][1] = fexp2(sacc[nt][1] - m_a);
            sacc[nt][2] = fexp2(sacc[nt][2] - m_b);
            sacc[nt][3] = fexp2(sacc[nt][3] - m_b);
            sa  += sacc[nt][0] + sacc[nt][1];
            sbm += sacc[nt][2] + sacc[nt][3];
        }
        l_a = l_a * ala + sa;
        l_b = l_b * alb + sbm;
        #pragma unroll
        for (int nt2 = 0; nt2 < 16; nt2++) {
            oacc[nt2][0] *= ala; oacc[nt2][1] *= ala;
            oacc[nt2][2] *= alb; oacc[nt2][3] *= alb;
        }

        uint32_t pA[4][4];
        #pragma unroll
        for (int kt = 0; kt < 4; kt++) {
            pA[kt][0] = pack_h2(sacc[2*kt][0],   sacc[2*kt][1]);
            pA[kt][1] = pack_h2(sacc[2*kt][2],   sacc[2*kt][3]);
            pA[kt][2] = pack_h2(sacc[2*kt+1][0], sacc[2*kt+1][1]);
            pA[kt][3] = pack_h2(sacc[2*kt+1][2], sacc[2*kt+1][3]);
        }

        const uint32_t bvb = vbase + (uint32_t)((lane & 15) * FSTRB);
        #pragma unroll
        for (int kt = 0; kt < 4; kt++) {
            #pragma unroll
            for (int nt2 = 0; nt2 < 16; nt2++) {
                uint32_t bv[2];
                ldsm_x2t(bv, bvb + (uint32_t)(kt * 16 * FSTRB) + nt2 * 16);
                mma_f16(oacc[nt2], pA[kt], bv);
            }
        }
        __syncthreads();
    }

    #pragma unroll
    for (int o = 1; o < 4; o <<= 1) {
        l_a += __shfl_xor_sync(0xffffffffu, l_a, o);
        l_b += __shfl_xor_sync(0xffffffffu, l_b, o);
    }
    const float inva = 1.0f / l_a, invb = 1.0f / l_b;

    const int ra = q0 + w * 16 + (lane >> 2);
    float* Oa = ctx + ((size_t)(b * SEQ + ra)) * EMB + h * HDIM + (lane & 3) * 2;
    float* Ob = ctx + ((size_t)(b * SEQ + ra + 8)) * EMB + h * HDIM + (lane & 3) * 2;
    #pragma unroll
    for (int nt2 = 0; nt2 < 16; nt2++) {
        *(float2*)(Oa + nt2 * 8) = make_float2(oacc[nt2][0] * inva, oacc[nt2][1] * inva);
        *(float2*)(Ob + nt2 * 8) = make_float2(oacc[nt2][2] * invb, oacc[nt2][3] * invb);
    }
}

// ============================================================================
// launch
// ============================================================================
extern "C" void kernel_launch(void* const* d_in, const int* in_sizes, int n_in,
                              void* d_out, int out_size)
{
    const float* x    = (const float*)d_in[0];
    const float* mask = (const float*)d_in[1];
    const float* Wq   = (const float*)d_in[2];
    const float* Wk   = (const float*)d_in[3];
    const float* Wv   = (const float*)d_in[4];
    const float* Wo   = (const float*)d_in[5];
    float* out = (float*)d_out;

    float *qkvp, *cxp;
    __half *qhp, *khp, *vhp, *axp, *wqkvp, *wosp;
    cudaGetSymbolAddress((void**)&qkvp, g_QKV);
    cudaGetSymbolAddress((void**)&cxp,  g_ctx);
    cudaGetSymbolAddress((void**)&qhp,  g_Qh);
    cudaGetSymbolAddress((void**)&khp,  g_Kh);
    cudaGetSymbolAddress((void**)&vhp,  g_Vh);
    cudaGetSymbolAddress((void**)&axp,  g_Ax);
    cudaGetSymbolAddress((void**)&wqkvp, g_Wqkv);
    cudaGetSymbolAddress((void**)&wosp, g_Wos);

    // splits: x -> [hi,lo]; weights -> [hi,hi] into concatenated QKV buffer
    split_f16<<<(MTOT * 512) / 256, 256>>>(x, axp, 1);
    split_f16<<<(EMB * 512) / 256, 256>>>(Wq, wqkvp, 0);
    split_f16<<<(EMB * 512) / 256, 256>>>(Wk, wqkvp + (size_t)EMB * KP2, 0);
    split_f16<<<(EMB * 512) / 256, 256>>>(Wv, wqkvp + (size_t)2 * EMB * KP2, 0);
    split_f16<<<(EMB * 512) / 256, 256>>>(Wo, wosp, 0);

    cudaFuncSetAttribute(gemm_f16s, cudaFuncAttributeMaxDynamicSharedMemorySize, G_SMEM);
    // fused QKV GEMM: C[4096, 6144]
    gemm_f16s<<<dim3(3 * EMB / 128, MTOT / 128), 256, G_SMEM>>>(axp, wqkvp, qkvp, 3 * EMB);

    rope_half<<<(MTOT * 1024) / 256, 256>>>(qkvp, qhp, khp);
    v_half<<<(MTOT * 512) / 256, 256>>>(qkvp, vhp);

    cudaFuncSetAttribute(flash_hmma, cudaFuncAttributeMaxDynamicSharedMemorySize, FSMEM);
    flash_hmma<<<dim3(SEQ / 128, NHEAD, BATCH), 256, FSMEM>>>(qhp, khp, vhp, mask, cxp);

    split_f16<<<(MTOT * 512) / 256, 256>>>(cxp, axp, 1);
    gemm_f16s<<<dim3(EMB / 128, MTOT / 128), 256, G_SMEM>>>(axp, wosp, out, EMB);
}